// round 14
// baseline (speedup 1.0000x reference)
#include <cuda_runtime.h>
#include <cstdint>

#define CST 46352   // padded channel stride = 34^3 + 18^3 + 10^3 + 6^3

__device__ float g_in36[36 * CST];
__device__ float g_buf[2][2][64 * CST];   // [head][pingpong]
__device__ float g_mean[512];             // [head][L][c]
__device__ float g_rstd[512];
__device__ float g_part[2 * 64 * 38 * 2]; // [head][oc][tile][s,q]

__device__ __forceinline__ void cp4(uint32_t d, const float* s) {
    asm volatile("cp.async.ca.shared.global [%0], [%1], 4;" :: "r"(d), "l"(s));
}
#define CP_COMMIT() asm volatile("cp.async.commit_group;" ::: "memory")
#define CP_WAIT0()  asm volatile("cp.async.wait_group 0;" ::: "memory")

// ---------------------------------------------------------------------------
__global__ void pack_kernel(const float* __restrict__ p0, const float* __restrict__ p1,
                            const float* __restrict__ p2, const float* __restrict__ p3,
                            float* __restrict__ out) {
    int c = blockIdx.y;
    int pos = blockIdx.x * 256 + threadIdx.x;
    if (pos >= 37440) return;
    const float* p; int v, S, PS, OF, lg;
    if (pos < 32768)      { p = p0; v = pos;         S = 32; PS = 34; OF = 0;     lg = 5; }
    else if (pos < 36864) { p = p1; v = pos - 32768; S = 16; PS = 18; OF = 39304; lg = 4; }
    else if (pos < 37376) { p = p2; v = pos - 36864; S = 8;  PS = 10; OF = 45136; lg = 3; }
    else                  { p = p3; v = pos - 37376; S = 4;  PS = 6;  OF = 46136; lg = 2; }
    int w = v & (S - 1), h = (v >> lg) & (S - 1), d = v >> (2 * lg);
    out[c * CST + OF + ((d + 1) * PS + h + 1) * PS + (w + 1)] =
        p[c * (S * S * S) + v];
}

// ---------------------------------------------------------------------------
__global__ void reduce_kernel(float* __restrict__ mean, float* __restrict__ rstd) {
    int head = blockIdx.x >> 8, sub = blockIdx.x & 255;
    int L = sub >> 6, c = sub & 63;
    const int basev[4] = {0, 32, 36, 37}, cntv[4] = {32, 4, 1, 1};
    const float invN[4] = {1.f / 32768.f, 1.f / 4096.f, 1.f / 512.f, 1.f / 64.f};
    int t = threadIdx.x;
    float s = 0.f, q = 0.f;
    if (t < cntv[L]) {
        int idx = (((head << 6) + c) * 38 + basev[L] + t) * 2;
        s = g_part[idx];
        q = g_part[idx + 1];
    }
#pragma unroll
    for (int o = 16; o > 0; o >>= 1) {
        s += __shfl_down_sync(0xffffffffu, s, o);
        q += __shfl_down_sync(0xffffffffu, q, o);
    }
    if (t == 0) {
        float m = s * invN[L];
        float v = q * invN[L] - m * m;
        mean[blockIdx.x] = m;
        rstd[blockIdx.x] = rsqrtf(fmaxf(v, 0.f) + 1e-5f);
    }
}

// ---------------------------------------------------------------------------
// In-place InstanceNorm + PReLU, voxel-parallel. grid = (147, 64, 2 heads).
// ---------------------------------------------------------------------------
__global__ void np_kernel(float* __restrict__ b0, float* __restrict__ b1,
                          const float* __restrict__ mean, const float* __restrict__ rstd,
                          const float* __restrict__ a0, const float* __restrict__ a1,
                          int aidx) {
    int c = blockIdx.y, head = blockIdx.z;
    int pos = blockIdx.x * 256 + threadIdx.x;
    if (pos >= 37440) return;
    int v, S, PS, OF, lg, L;
    if (pos < 32768)      { v = pos;         S = 32; PS = 34; OF = 0;     lg = 5; L = 0; }
    else if (pos < 36864) { v = pos - 32768; S = 16; PS = 18; OF = 39304; lg = 4; L = 1; }
    else if (pos < 37376) { v = pos - 36864; S = 8;  PS = 10; OF = 45136; lg = 3; L = 2; }
    else                  { v = pos - 37376; S = 4;  PS = 6;  OF = 46136; lg = 2; L = 3; }
    int w = v & (S - 1), h = (v >> lg) & (S - 1), d = v >> (2 * lg);
    float* p = (head ? b1 : b0) + c * CST + OF + ((d + 1) * PS + h + 1) * PS + (w + 1);
    int si = head * 256 + L * 64 + c;
    float m = __ldg(mean + si), r = __ldg(rstd + si);
    float alpha = __ldg((head ? a1 : a0) + aidx);
    float x = (*p - m) * r;
    *p = x >= 0.f ? x : alpha * x;
}

// ---------------------------------------------------------------------------
template <int LEV> struct Geo8;
template <> struct Geo8<0> { enum { S = 32, PS = 34, OFF = 0,     ZT = 6,  YT = 10, XT = 34, XP = 36 }; };
template <> struct Geo8<1> { enum { S = 16, PS = 18, OFF = 39304, ZT = 6,  YT = 18, XT = 18, XP = 20 }; };
template <> struct Geo8<2> { enum { S = 8,  PS = 10, OFF = 45136, ZT = 10, YT = 10, XT = 10, XP = 12 }; };
template <> struct Geo8<3> { enum { S = 4,  PS = 6,  OFF = 46136, ZT = 6,  YT = 6,  XT = 6,  XP = 12 }; };

template <int LEV> struct Geo4;
template <> struct Geo4<0> { enum { S = 32, PS = 34, OFF = 0,     VOX = 0,     ZT = 4,  YT = 10, XT = 34, XP = 36 }; };
template <> struct Geo4<1> { enum { S = 16, PS = 18, OFF = 39304, VOX = 32768, ZT = 6,  YT = 10, XT = 18, XP = 20 }; };
template <> struct Geo4<2> { enum { S = 8,  PS = 10, OFF = 45136, VOX = 36864, ZT = 10, YT = 10, XT = 10, XP = 12 }; };
template <> struct Geo4<3> { enum { S = 4,  PS = 6,  OFF = 46136, VOX = 37376, ZT = 6,  YT = 6,  XT = 6,  XP = 8  }; };

// ---------------------------------------------------------------------------
template <int LEV>
__device__ __forceinline__ void map8(int wg, int sp, int& tz, int& ty, int& tx,
                                     int& d0, int& h0, bool& active) {
    d0 = 0; h0 = 0; active = true;
    if (LEV == 0) { tx = wg & 3; ty = (wg >> 2) & 7; tz = wg >> 5;
                    d0 = (sp >> 2) * 4; h0 = (sp & 3) * 8; }
    else if (LEV == 1) { tx = wg & 1; ty = (wg >> 1) & 15; tz = wg >> 5;
                    d0 = sp * 4; }
    else if (LEV == 2) { tx = 0; ty = wg & 7; tz = (wg >> 3) & 7; active = (wg < 64); }
    else { tx = 0; ty = wg & 3; tz = (wg >> 2) & 3; active = (wg < 16); }
}

// ---------------------------------------------------------------------------
// VW=8 conv body (main layers). 256 threads = 2 halves x 8 oc. cp.async
// staging, padded layout, double-buffered, one barrier per ic.
// Epilogue: output + per-(half, oc) stats partials -> g_part.
// ---------------------------------------------------------------------------
template <int LEV>
__device__ __forceinline__ void conv_body8(
    int sp, int ocg, int head, int r,
    const float* __restrict__ in, const float* __restrict__ wgt,
    const float* __restrict__ bias, float* __restrict__ out,
    int CIN, float* __restrict__ in_s, float* __restrict__ w_s) {

    typedef Geo8<LEV> G;
    constexpr int PS = G::PS, OFF = G::OFF;
    constexpr int ZT = G::ZT, YT = G::YT, XT = G::XT, XP = G::XP;
    constexpr int TILE = ZT * YT * XP;
    constexpr int TOTE = ZT * YT * XT;
    constexpr int NL   = (TOTE + 255) / 256;
    constexpr int VV   = (LEV == 3) ? 4 : 8;

    const int t  = threadIdx.x;
    const int wg = t & 127;

    int tz, ty, tx, d0, h0;
    bool active;
    map8<LEV>(wg, sp, tz, ty, tx, d0, h0, active);

    int goff[NL], sbyte[NL];
#pragma unroll
    for (int i = 0; i < NL; ++i) {
        int idx = i * 256 + t;
        sbyte[i] = -1;
        if (idx < TOTE) {
            int z = idx / (YT * XT), rem = idx - z * (YT * XT);
            int y = rem / XT, x = rem - y * XT;
            goff[i]  = ((d0 + z) * PS + (h0 + y)) * PS + x;
            sbyte[i] = ((z * YT + y) * XP + x) * 4;
        }
    }
    int wgoff[2];
    bool wok[2];
#pragma unroll
    for (int p = 0; p < 2; ++p) {
        int i = p * 128 + wg;
        wgoff[p] = 0; wok[p] = false;
        if (i < 216) {
            wgoff[p] = ((ocg * 8 + (i & 7)) * CIN) * 27 + (i >> 3);
            wok[p] = true;
        }
    }

    const uint32_t in_sa = (uint32_t)__cvta_generic_to_shared(in_s);
    const uint32_t w_sa  = (uint32_t)__cvta_generic_to_shared(w_s);

    float acc[8][8];
#pragma unroll
    for (int j = 0; j < 8; ++j)
#pragma unroll
        for (int k = 0; k < 8; ++k) acc[j][k] = 0.f;

    const float* inb = in + OFF;

    auto issue = [&](int b, int ic) {
        const float* src = inb + ic * CST;
#pragma unroll
        for (int i = 0; i < NL; ++i)
            if (sbyte[i] >= 0) cp4(in_sa + b * (TILE * 4) + sbyte[i], src + goff[i]);
#pragma unroll
        for (int p = 0; p < 2; ++p)
            if (wok[p]) cp4(w_sa + b * (216 * 4) + (p * 128 + wg) * 4,
                            wgt + ic * 27 + wgoff[p]);
    };

    issue(0, 0);
    CP_COMMIT();
    CP_WAIT0();
    __syncthreads();

    const int x0 = tx << 3;
    for (int ic = 0; ic < CIN; ++ic) {
        int cur = ic & 1, nb = cur ^ 1;
        if (ic + 1 < CIN) { issue(nb, ic + 1); CP_COMMIT(); }

        if (active) {
            const float* buf = in_s + cur * TILE;
            const float* wb  = w_s + cur * 216;
#pragma unroll
            for (int kz = 0; kz < 3; ++kz) {
#pragma unroll
                for (int ky = 0; ky < 3; ++ky) {
                    const float* ip = &buf[((tz + kz) * YT + (ty + ky)) * XP + x0];
                    float4 xa = *(const float4*)ip;
                    float4 xb = *(const float4*)(ip + 4);
                    float2 xc = *(const float2*)(ip + 8);
                    float x[10] = {xa.x, xa.y, xa.z, xa.w,
                                   xb.x, xb.y, xb.z, xb.w, xc.x, xc.y};

                    const float* wt = wb + (kz * 3 + ky) * 24;
                    float w0a[8], w1a[8], w2a[8];
                    *(float4*)&w0a[0] = *(const float4*)(wt);
                    *(float4*)&w0a[4] = *(const float4*)(wt + 4);
                    *(float4*)&w1a[0] = *(const float4*)(wt + 8);
                    *(float4*)&w1a[4] = *(const float4*)(wt + 12);
                    *(float4*)&w2a[0] = *(const float4*)(wt + 16);
                    *(float4*)&w2a[4] = *(const float4*)(wt + 20);
#pragma unroll
                    for (int j = 0; j < 8; ++j) {
                        float w0 = w0a[j], w1 = w1a[j], w2 = w2a[j];
#pragma unroll
                        for (int k = 0; k < 8; ++k) {
                            acc[j][k] = fmaf(x[k],     w0, acc[j][k]);
                            acc[j][k] = fmaf(x[k + 1], w1, acc[j][k]);
                            acc[j][k] = fmaf(x[k + 2], w2, acc[j][k]);
                        }
                    }
                }
            }
        }

        if (ic + 1 < CIN) CP_WAIT0();
        __syncthreads();
    }

    // ---- output store + stats partials ----
    float s8[8], q8[8];
#pragma unroll
    for (int j = 0; j < 8; ++j) { s8[j] = 0.f; q8[j] = 0.f; }

    if (active) {
        int d = d0 + tz, h = h0 + ty;
        int pidx = ((d + 1) * PS + (h + 1)) * PS + (x0 + 1);
#pragma unroll
        for (int j = 0; j < 8; ++j) {
            int oc = ocg * 8 + j;
            float b = bias[oc];
            float* o = out + oc * CST + OFF + pidx;
#pragma unroll
            for (int k = 0; k < VV; ++k) {
                float ov = acc[j][k] + b;
                o[k] = ov;
                s8[j] += ov;
                q8[j] = fmaf(ov, ov, q8[j]);
            }
        }
    }

#pragma unroll
    for (int j = 0; j < 8; ++j) {
#pragma unroll
        for (int o = 16; o > 0; o >>= 1) {
            s8[j] += __shfl_down_sync(0xffffffffu, s8[j], o);
            q8[j] += __shfl_down_sync(0xffffffffu, q8[j], o);
        }
    }
    int warp = wg >> 5, lane = t & 31;
    if (lane == 0) {
#pragma unroll
        for (int j = 0; j < 8; ++j) {
            w_s[warp * 16 + j * 2]     = s8[j];
            w_s[warp * 16 + j * 2 + 1] = q8[j];
        }
    }
    __syncthreads();
    if (wg < 8) {
        int j = wg;
        float s = 0.f, q = 0.f;
#pragma unroll
        for (int w2 = 0; w2 < 4; ++w2) {
            s += w_s[w2 * 16 + j * 2];
            q += w_s[w2 * 16 + j * 2 + 1];
        }
        int oc = ocg * 8 + j;
        int idx = (((head << 6) + oc) * 38 + r) * 2;
        g_part[idx]     = s;
        g_part[idx + 1] = q;
    }
}

// ---------------------------------------------------------------------------
template <int DUMMY>
__global__ void __launch_bounds__(256, 2) conv_k8(
    const float* __restrict__ in0, const float* __restrict__ in1,
    const float* __restrict__ w0, const float* __restrict__ w1,
    const float* __restrict__ b0, const float* __restrict__ b1,
    float* __restrict__ out0, float* __restrict__ out1,
    int CIN, int g0) {

    __shared__ __align__(16) float in_s[2 * 2160];
    __shared__ __align__(16) float w_s[2 * 2 * 216];

    int gidx = blockIdx.x / 38;
    int r    = blockIdx.x - gidx * 38;
    int half = threadIdx.x >> 7;
    int head = (gidx >= g0);
    int lg   = head ? gidx - g0 : gidx;
    int ocg  = lg * 2 + half;

    const float* in   = head ? in1 : in0;
    const float* wgt  = head ? w1  : w0;
    const float* bias = head ? b1  : b0;
    float*       out  = head ? out1 : out0;
    float* wsl = w_s + half * (2 * 216);

    if (r < 32)
        conv_body8<0>(r, ocg, head, r, in, wgt, bias, out, CIN, in_s, wsl);
    else if (r < 36)
        conv_body8<1>(r - 32, ocg, head, r, in, wgt, bias, out, CIN, in_s, wsl);
    else if (r == 36)
        conv_body8<2>(0, ocg, head, r, in, wgt, bias, out, CIN, in_s, wsl);
    else
        conv_body8<3>(0, ocg, head, r, in, wgt, bias, out, CIN, in_s, wsl);
}

// ---------------------------------------------------------------------------
// Final conv: VW=4 x OCW=9, 128 threads, channels-last output to d_out.
// Exact oc tiling: cls 18 = 2x9, reg 54 = 6x9 -> 8 grid-groups, no waste.
// Weight smem [27 taps][12] (OCP=12 for 16B-aligned LDS.128), slots j>=9 zero.
// ---------------------------------------------------------------------------
template <int LEV>
__device__ __forceinline__ void conv_final9(
    int sp, int ocg,
    const float* __restrict__ in, const float* __restrict__ wgt,
    const float* __restrict__ bias, float* __restrict__ out,
    int CIN, int COUT, int head_base,
    float* __restrict__ in_s, float* __restrict__ w_s) {

    typedef Geo4<LEV> G;
    constexpr int S = G::S, PS = G::PS, OFF = G::OFF, VOX = G::VOX;
    constexpr int ZT = G::ZT, YT = G::YT, XT = G::XT, XP = G::XP;
    constexpr int TILE = ZT * YT * XP;
    constexpr int TOTE = ZT * YT * XT;
    constexpr int NL   = (TOTE + 127) / 128;
    constexpr int WSLP = 27 * 12;   // 324

    const int t = threadIdx.x;
    int tz, ty, tx, d0 = 0, h0 = 0;
    bool active = true;
    if (LEV == 0) { tx = t & 7; ty = (t >> 3) & 7; tz = t >> 6;
                    d0 = (sp >> 2) * 2; h0 = (sp & 3) * 8; }
    else if (LEV == 1) { tx = t & 3; ty = (t >> 2) & 7; tz = t >> 5;
                    d0 = (sp >> 1) * 4; h0 = (sp & 1) * 8; }
    else if (LEV == 2) { tx = t & 1; ty = (t >> 1) & 7; tz = t >> 4; }
    else { tx = 0; ty = t & 3; tz = (t >> 2) & 3; active = (t < 16); }

    int goff[NL], sbyte[NL];
#pragma unroll
    for (int i = 0; i < NL; ++i) {
        int idx = i * 128 + t;
        sbyte[i] = -1;
        if (idx < TOTE) {
            int z = idx / (YT * XT), rem = idx - z * (YT * XT);
            int y = rem / XT, x = rem - y * XT;
            goff[i]  = ((d0 + z) * PS + (h0 + y)) * PS + x;
            sbyte[i] = ((z * YT + y) * XP + x) * 4;
        }
    }
    int wgoff[3];
    bool wok[3];
#pragma unroll
    for (int p = 0; p < 3; ++p) {
        int i = p * 128 + t;
        wgoff[p] = 0; wok[p] = false;
        if (i < WSLP) {
            int k = i / 12, j = i - k * 12;
            if (j < 9) {
                int oc = ocg * 9 + j;
                wgoff[p] = (oc * CIN) * 27 + k;
                wok[p] = true;
            }
        }
    }

    const uint32_t in_sa = (uint32_t)__cvta_generic_to_shared(in_s);
    const uint32_t w_sa  = (uint32_t)__cvta_generic_to_shared(w_s);

    float acc[9][4];
#pragma unroll
    for (int j = 0; j < 9; ++j) {
        acc[j][0] = 0.f; acc[j][1] = 0.f; acc[j][2] = 0.f; acc[j][3] = 0.f;
    }

    const float* inb = in + OFF;

    // zero the padded weight slots once (j >= 9 entries stay zero)
    for (int i = t; i < 2 * WSLP; i += 128) w_s[i] = 0.f;
    __syncthreads();

    auto issue = [&](int b, int ic) {
        const float* src = inb + ic * CST;
#pragma unroll
        for (int i = 0; i < NL; ++i)
            if (sbyte[i] >= 0) cp4(in_sa + b * (TILE * 4) + sbyte[i], src + goff[i]);
#pragma unroll
        for (int p = 0; p < 3; ++p)
            if (wok[p]) cp4(w_sa + b * (WSLP * 4) + (p * 128 + t) * 4,
                            wgt + ic * 27 + wgoff[p]);
    };

    issue(0, 0);
    CP_COMMIT();
    CP_WAIT0();
    __syncthreads();

    for (int ic = 0; ic < CIN; ++ic) {
        int cur = ic & 1, nb = cur ^ 1;
        if (ic + 1 < CIN) { issue(nb, ic + 1); CP_COMMIT(); }

        if (active) {
            const float* buf = in_s + cur * TILE;
            const float* wb  = w_s + cur * WSLP;
#pragma unroll
            for (int kz = 0; kz < 3; ++kz) {
#pragma unroll
                for (int ky = 0; ky < 3; ++ky) {
                    const float* ip = &buf[((tz + kz) * YT + (ty + ky)) * XP + (tx << 2)];
                    float4 xa = *(const float4*)ip;
                    float2 xb = *(const float2*)(ip + 4);
                    float x0 = xa.x, x1 = xa.y, x2 = xa.z;
                    float x3 = xa.w, x4 = xb.x, x5 = xb.y;

                    const float* wt = wb + (kz * 3 + ky) * 36;
                    float w0a[12], w1a[12], w2a[12];
                    *(float4*)&w0a[0] = *(const float4*)(wt);
                    *(float4*)&w0a[4] = *(const float4*)(wt + 4);
                    *(float4*)&w0a[8] = *(const float4*)(wt + 8);
                    *(float4*)&w1a[0] = *(const float4*)(wt + 12);
                    *(float4*)&w1a[4] = *(const float4*)(wt + 16);
                    *(float4*)&w1a[8] = *(const float4*)(wt + 20);
                    *(float4*)&w2a[0] = *(const float4*)(wt + 24);
                    *(float4*)&w2a[4] = *(const float4*)(wt + 28);
                    *(float4*)&w2a[8] = *(const float4*)(wt + 32);
#pragma unroll
                    for (int j = 0; j < 9; ++j) {
                        float w0 = w0a[j], w1 = w1a[j], w2 = w2a[j];
                        acc[j][0] = fmaf(x0, w0, acc[j][0]);
                        acc[j][1] = fmaf(x1, w0, acc[j][1]);
                        acc[j][2] = fmaf(x2, w0, acc[j][2]);
                        acc[j][3] = fmaf(x3, w0, acc[j][3]);
                        acc[j][0] = fmaf(x1, w1, acc[j][0]);
                        acc[j][1] = fmaf(x2, w1, acc[j][1]);
                        acc[j][2] = fmaf(x3, w1, acc[j][2]);
                        acc[j][3] = fmaf(x4, w1, acc[j][3]);
                        acc[j][0] = fmaf(x2, w2, acc[j][0]);
                        acc[j][1] = fmaf(x3, w2, acc[j][1]);
                        acc[j][2] = fmaf(x4, w2, acc[j][2]);
                        acc[j][3] = fmaf(x5, w2, acc[j][3]);
                    }
                }
            }
        }

        if (ic + 1 < CIN) CP_WAIT0();
        __syncthreads();
    }

    if (!active) return;
    int d = d0 + tz, h = h0 + ty, w0i = tx << 2;
    int vidx = (d * S + h) * S + w0i;
#pragma unroll
    for (int j = 0; j < 9; ++j) {
        int oc = ocg * 9 + j;
        float b = bias[oc];
        int base = head_base + (VOX + vidx) * COUT + oc;
        out[base + 0 * COUT] = acc[j][0] + b;
        out[base + 1 * COUT] = acc[j][1] + b;
        out[base + 2 * COUT] = acc[j][2] + b;
        out[base + 3 * COUT] = acc[j][3] + b;
    }
}

// ---------------------------------------------------------------------------
template <int DUMMY>
__global__ void __launch_bounds__(128) conv_kf(
    const float* __restrict__ in0, const float* __restrict__ in1,
    const float* __restrict__ w0, const float* __restrict__ w1,
    const float* __restrict__ b0, const float* __restrict__ b1,
    float* __restrict__ out,
    int CIN, int COUT0, int COUT1, int g0, int base1) {

    __shared__ __align__(16) float in_s[2 * 1440];
    __shared__ __align__(16) float w_s[2 * 324];

    int gidx = blockIdx.x / 74;
    int r    = blockIdx.x - gidx * 74;
    int head = (gidx >= g0);
    int ocg  = head ? gidx - g0 : gidx;

    const float* in   = head ? in1 : in0;
    const float* wgt  = head ? w1  : w0;
    const float* bias = head ? b1  : b0;
    int COUT  = head ? COUT1 : COUT0;
    int hbase = head ? base1 : 0;

    if (r < 64)
        conv_final9<0>(r, ocg, in, wgt, bias, out, CIN, COUT, hbase, in_s, w_s);
    else if (r < 72)
        conv_final9<1>(r - 64, ocg, in, wgt, bias, out, CIN, COUT, hbase, in_s, w_s);
    else if (r == 72)
        conv_final9<2>(0, ocg, in, wgt, bias, out, CIN, COUT, hbase, in_s, w_s);
    else
        conv_final9<3>(0, ocg, in, wgt, bias, out, CIN, COUT, hbase, in_s, w_s);
}

// ---------------------------------------------------------------------------
extern "C" void kernel_launch(void* const* d_in, const int* in_sizes, int n_in,
                              void* d_out, int out_size) {
    (void)in_sizes; (void)n_in; (void)out_size;

    const float* p0 = (const float*)d_in[0];
    const float* p1 = (const float*)d_in[1];
    const float* p2 = (const float*)d_in[2];
    const float* p3 = (const float*)d_in[3];

    const float* cw1   = (const float*)d_in[4];
    const float* cb1   = (const float*)d_in[5];
    const float* cw234 = (const float*)d_in[6];
    const float* cb234 = (const float*)d_in[7];
    const float* ca    = (const float*)d_in[8];
    const float* cwf   = (const float*)d_in[9];
    const float* cbf   = (const float*)d_in[10];
    const float* rw1   = (const float*)d_in[11];
    const float* rb1   = (const float*)d_in[12];
    const float* rw234 = (const float*)d_in[13];
    const float* rb234 = (const float*)d_in[14];
    const float* ra    = (const float*)d_in[15];
    const float* rwf   = (const float*)d_in[16];
    const float* rbf   = (const float*)d_in[17];

    float *in36, *buf, *mean, *rstd;
    cudaGetSymbolAddress((void**)&in36, g_in36);
    cudaGetSymbolAddress((void**)&buf,  g_buf);
    cudaGetSymbolAddress((void**)&mean, g_mean);
    cudaGetSymbolAddress((void**)&rstd, g_rstd);

    float* A0 = buf;
    float* B0 = buf + (size_t)64 * CST;
    float* A1 = buf + (size_t)2 * 64 * CST;
    float* B1 = buf + (size_t)3 * 64 * CST;
    float* out = (float*)d_out;
    const int CLS_TOTAL = 37440 * 18;

    pack_kernel<<<dim3(147, 36), 256>>>(p0, p1, p2, p3, in36);

    // conv1 (36->64, raw input); epilogue writes stats partials
    conv_k8<0><<<8 * 38, 256>>>(in36, in36, cw1, rw1, cb1, rb1, A0, A1, 36, 4);
    reduce_kernel<<<512, 32>>>(mean, rstd);
    np_kernel<<<dim3(147, 64, 2), 256>>>(A0, A1, mean, rstd, ca, ra, 0);

    float* s0 = A0; float* d0p = B0;
    float* s1 = A1; float* d1p = B1;
    for (int i = 0; i < 3; ++i) {
        conv_k8<0><<<8 * 38, 256>>>(
            s0, s1, cw234 + (size_t)i * 64 * 64 * 27, rw234 + (size_t)i * 64 * 64 * 27,
            cb234 + i * 64, rb234 + i * 64, d0p, d1p, 64, 4);
        reduce_kernel<<<512, 32>>>(mean, rstd);
        np_kernel<<<dim3(147, 64, 2), 256>>>(d0p, d1p, mean, rstd, ca, ra, i + 1);
        float* t0 = s0; s0 = d0p; d0p = t0;
        float* t1 = s1; s1 = d1p; d1p = t1;
    }

    // final conv VW4/OCW9, exact tiling: cls 2 groups, reg 6 groups
    conv_kf<0><<<8 * 74, 128>>>(
        s0, s1, cwf, rwf, cbf, rbf, out, 64, 18, 54, 2, CLS_TOTAL);
}

// round 15
// speedup vs baseline: 1.0436x; 1.0436x over previous
#include <cuda_runtime.h>
#include <cstdint>

#define CST 46352   // padded channel stride = 34^3 + 18^3 + 10^3 + 6^3

__device__ float g_buf[2][2][64 * CST];   // [head][pingpong]
__device__ float g_mean[512];             // [head][L][c]
__device__ float g_rstd[512];
__device__ float g_part[2 * 64 * 38 * 2]; // [head][oc][tile][s,q]

__device__ __forceinline__ void cp4(uint32_t d, const float* s) {
    asm volatile("cp.async.ca.shared.global [%0], [%1], 4;" :: "r"(d), "l"(s));
}
#define CP_COMMIT() asm volatile("cp.async.commit_group;" ::: "memory")
#define CP_WAIT0()  asm volatile("cp.async.wait_group 0;" ::: "memory")

// ---------------------------------------------------------------------------
__global__ void reduce_kernel(float* __restrict__ mean, float* __restrict__ rstd) {
    int head = blockIdx.x >> 8, sub = blockIdx.x & 255;
    int L = sub >> 6, c = sub & 63;
    const int basev[4] = {0, 32, 36, 37}, cntv[4] = {32, 4, 1, 1};
    const float invN[4] = {1.f / 32768.f, 1.f / 4096.f, 1.f / 512.f, 1.f / 64.f};
    int t = threadIdx.x;
    float s = 0.f, q = 0.f;
    if (t < cntv[L]) {
        int idx = (((head << 6) + c) * 38 + basev[L] + t) * 2;
        s = g_part[idx];
        q = g_part[idx + 1];
    }
#pragma unroll
    for (int o = 16; o > 0; o >>= 1) {
        s += __shfl_down_sync(0xffffffffu, s, o);
        q += __shfl_down_sync(0xffffffffu, q, o);
    }
    if (t == 0) {
        float m = s * invN[L];
        float v = q * invN[L] - m * m;
        mean[blockIdx.x] = m;
        rstd[blockIdx.x] = rsqrtf(fmaxf(v, 0.f) + 1e-5f);
    }
}

// ---------------------------------------------------------------------------
// In-place InstanceNorm + PReLU, voxel-parallel. grid = (147, 64, 2 heads).
// ---------------------------------------------------------------------------
__global__ void np_kernel(float* __restrict__ b0, float* __restrict__ b1,
                          const float* __restrict__ mean, const float* __restrict__ rstd,
                          const float* __restrict__ a0, const float* __restrict__ a1,
                          int aidx) {
    int c = blockIdx.y, head = blockIdx.z;
    int pos = blockIdx.x * 256 + threadIdx.x;
    if (pos >= 37440) return;
    int v, S, PS, OF, lg, L;
    if (pos < 32768)      { v = pos;         S = 32; PS = 34; OF = 0;     lg = 5; L = 0; }
    else if (pos < 36864) { v = pos - 32768; S = 16; PS = 18; OF = 39304; lg = 4; L = 1; }
    else if (pos < 37376) { v = pos - 36864; S = 8;  PS = 10; OF = 45136; lg = 3; L = 2; }
    else                  { v = pos - 37376; S = 4;  PS = 6;  OF = 46136; lg = 2; L = 3; }
    int w = v & (S - 1), h = (v >> lg) & (S - 1), d = v >> (2 * lg);
    float* p = (head ? b1 : b0) + c * CST + OF + ((d + 1) * PS + h + 1) * PS + (w + 1);
    int si = head * 256 + L * 64 + c;
    float m = __ldg(mean + si), r = __ldg(rstd + si);
    float alpha = __ldg((head ? a1 : a0) + aidx);
    float x = (*p - m) * r;
    *p = x >= 0.f ? x : alpha * x;
}

// ---------------------------------------------------------------------------
template <int LEV> struct Geo8;
template <> struct Geo8<0> { enum { S = 32, PS = 34, OFF = 0,     ZT = 6,  YT = 10, XT = 34, XP = 36 }; };
template <> struct Geo8<1> { enum { S = 16, PS = 18, OFF = 39304, ZT = 6,  YT = 18, XT = 18, XP = 20 }; };
template <> struct Geo8<2> { enum { S = 8,  PS = 10, OFF = 45136, ZT = 10, YT = 10, XT = 10, XP = 12 }; };
template <> struct Geo8<3> { enum { S = 4,  PS = 6,  OFF = 46136, ZT = 6,  YT = 6,  XT = 6,  XP = 12 }; };

template <int LEV> struct Geo4;
template <> struct Geo4<0> { enum { S = 32, PS = 34, OFF = 0,     VOX = 0,     ZT = 4,  YT = 10, XT = 34, XP = 36 }; };
template <> struct Geo4<1> { enum { S = 16, PS = 18, OFF = 39304, VOX = 32768, ZT = 6,  YT = 10, XT = 18, XP = 20 }; };
template <> struct Geo4<2> { enum { S = 8,  PS = 10, OFF = 45136, VOX = 36864, ZT = 10, YT = 10, XT = 10, XP = 12 }; };
template <> struct Geo4<3> { enum { S = 4,  PS = 6,  OFF = 46136, VOX = 37376, ZT = 6,  YT = 6,  XT = 6,  XP = 8  }; };

// ---------------------------------------------------------------------------
template <int LEV>
__device__ __forceinline__ void map8(int wg, int sp, int& tz, int& ty, int& tx,
                                     int& d0, int& h0, bool& active) {
    d0 = 0; h0 = 0; active = true;
    if (LEV == 0) { tx = wg & 3; ty = (wg >> 2) & 7; tz = wg >> 5;
                    d0 = (sp >> 2) * 4; h0 = (sp & 3) * 8; }
    else if (LEV == 1) { tx = wg & 1; ty = (wg >> 1) & 15; tz = wg >> 5;
                    d0 = sp * 4; }
    else if (LEV == 2) { tx = 0; ty = wg & 7; tz = (wg >> 3) & 7; active = (wg < 64); }
    else { tx = 0; ty = wg & 3; tz = (wg >> 2) & 3; active = (wg < 16); }
}

// ---------------------------------------------------------------------------
// VW=8 conv body. 256 threads = 2 halves x 8 oc. cp.async staging, double-
// buffered, one barrier per ic. RAW mode (conv1): source is the original
// unpadded level tensor (stride S^3); halo slots are skipped (sbyte=-1) and
// rely on once-pre-zeroed smem. Epilogue: output + stats partials -> g_part.
// ---------------------------------------------------------------------------
template <int LEV, bool RAW>
__device__ __forceinline__ void conv_body8(
    int sp, int ocg, int head, int r,
    const float* __restrict__ src0, const float* __restrict__ wgt,
    const float* __restrict__ bias, float* __restrict__ out,
    int CIN, float* __restrict__ in_s, float* __restrict__ w_s) {

    typedef Geo8<LEV> G;
    constexpr int S = G::S, PS = G::PS, OFF = G::OFF;
    constexpr int ZT = G::ZT, YT = G::YT, XT = G::XT, XP = G::XP;
    constexpr int TILE = ZT * YT * XP;
    constexpr int TOTE = ZT * YT * XT;
    constexpr int NL   = (TOTE + 255) / 256;
    constexpr int VV   = (LEV == 3) ? 4 : 8;
    constexpr int SSTRIDE = RAW ? (S * S * S) : CST;

    const int t  = threadIdx.x;
    const int wg = t & 127;

    int tz, ty, tx, d0, h0;
    bool active;
    map8<LEV>(wg, sp, tz, ty, tx, d0, h0, active);

    int goff[NL], sbyte[NL];
#pragma unroll
    for (int i = 0; i < NL; ++i) {
        int idx = i * 256 + t;
        sbyte[i] = -1;
        if (idx < TOTE) {
            int z = idx / (YT * XT), rem = idx - z * (YT * XT);
            int y = rem / XT, x = rem - y * XT;
            if (RAW) {
                int gz = d0 + z - 1, gy = h0 + y - 1, gx = x - 1;
                if ((unsigned)gz < (unsigned)S && (unsigned)gy < (unsigned)S &&
                    (unsigned)gx < (unsigned)S) {
                    goff[i]  = (gz * S + gy) * S + gx;
                    sbyte[i] = ((z * YT + y) * XP + x) * 4;
                }
            } else {
                goff[i]  = ((d0 + z) * PS + (h0 + y)) * PS + x;
                sbyte[i] = ((z * YT + y) * XP + x) * 4;
            }
        }
    }
    int wgoff[2];
    bool wok[2];
#pragma unroll
    for (int p = 0; p < 2; ++p) {
        int i = p * 128 + wg;
        wgoff[p] = 0; wok[p] = false;
        if (i < 216) {
            wgoff[p] = ((ocg * 8 + (i & 7)) * CIN) * 27 + (i >> 3);
            wok[p] = true;
        }
    }

    const uint32_t in_sa = (uint32_t)__cvta_generic_to_shared(in_s);
    const uint32_t w_sa  = (uint32_t)__cvta_generic_to_shared(w_s);

    float acc[8][8];
#pragma unroll
    for (int j = 0; j < 8; ++j)
#pragma unroll
        for (int k = 0; k < 8; ++k) acc[j][k] = 0.f;

    const float* base = RAW ? src0 : (src0 + OFF);

    auto issue = [&](int b, int ic) {
        const float* src = base + ic * SSTRIDE;
#pragma unroll
        for (int i = 0; i < NL; ++i)
            if (sbyte[i] >= 0) cp4(in_sa + b * (TILE * 4) + sbyte[i], src + goff[i]);
#pragma unroll
        for (int p = 0; p < 2; ++p)
            if (wok[p]) cp4(w_sa + b * (216 * 4) + (p * 128 + wg) * 4,
                            wgt + ic * 27 + wgoff[p]);
    };

    if (RAW) {
        for (int i = t; i < 2 * TILE; i += 256) in_s[i] = 0.f;
        __syncthreads();
    }

    issue(0, 0);
    CP_COMMIT();
    CP_WAIT0();
    __syncthreads();

    const int x0 = tx << 3;
    for (int ic = 0; ic < CIN; ++ic) {
        int cur = ic & 1, nb = cur ^ 1;
        if (ic + 1 < CIN) { issue(nb, ic + 1); CP_COMMIT(); }

        if (active) {
            const float* buf = in_s + cur * TILE;
            const float* wb  = w_s + cur * 216;
#pragma unroll
            for (int kz = 0; kz < 3; ++kz) {
#pragma unroll
                for (int ky = 0; ky < 3; ++ky) {
                    const float* ip = &buf[((tz + kz) * YT + (ty + ky)) * XP + x0];
                    float4 xa = *(const float4*)ip;
                    float4 xb = *(const float4*)(ip + 4);
                    float2 xc = *(const float2*)(ip + 8);
                    float x[10] = {xa.x, xa.y, xa.z, xa.w,
                                   xb.x, xb.y, xb.z, xb.w, xc.x, xc.y};

                    const float* wt = wb + (kz * 3 + ky) * 24;
                    float w0a[8], w1a[8], w2a[8];
                    *(float4*)&w0a[0] = *(const float4*)(wt);
                    *(float4*)&w0a[4] = *(const float4*)(wt + 4);
                    *(float4*)&w1a[0] = *(const float4*)(wt + 8);
                    *(float4*)&w1a[4] = *(const float4*)(wt + 12);
                    *(float4*)&w2a[0] = *(const float4*)(wt + 16);
                    *(float4*)&w2a[4] = *(const float4*)(wt + 20);
#pragma unroll
                    for (int j = 0; j < 8; ++j) {
                        float w0 = w0a[j], w1 = w1a[j], w2 = w2a[j];
#pragma unroll
                        for (int k = 0; k < 8; ++k) {
                            acc[j][k] = fmaf(x[k],     w0, acc[j][k]);
                            acc[j][k] = fmaf(x[k + 1], w1, acc[j][k]);
                            acc[j][k] = fmaf(x[k + 2], w2, acc[j][k]);
                        }
                    }
                }
            }
        }

        if (ic + 1 < CIN) CP_WAIT0();
        __syncthreads();
    }

    // ---- output store + stats partials ----
    float s8[8], q8[8];
#pragma unroll
    for (int j = 0; j < 8; ++j) { s8[j] = 0.f; q8[j] = 0.f; }

    if (active) {
        int d = d0 + tz, h = h0 + ty;
        int pidx = ((d + 1) * PS + (h + 1)) * PS + (x0 + 1);
#pragma unroll
        for (int j = 0; j < 8; ++j) {
            int oc = ocg * 8 + j;
            float b = bias[oc];
            float* o = out + oc * CST + OFF + pidx;
#pragma unroll
            for (int k = 0; k < VV; ++k) {
                float ov = acc[j][k] + b;
                o[k] = ov;
                s8[j] += ov;
                q8[j] = fmaf(ov, ov, q8[j]);
            }
        }
    }

#pragma unroll
    for (int j = 0; j < 8; ++j) {
#pragma unroll
        for (int o = 16; o > 0; o >>= 1) {
            s8[j] += __shfl_down_sync(0xffffffffu, s8[j], o);
            q8[j] += __shfl_down_sync(0xffffffffu, q8[j], o);
        }
    }
    int warp = wg >> 5, lane = t & 31;
    if (lane == 0) {
#pragma unroll
        for (int j = 0; j < 8; ++j) {
            w_s[warp * 16 + j * 2]     = s8[j];
            w_s[warp * 16 + j * 2 + 1] = q8[j];
        }
    }
    __syncthreads();
    if (wg < 8) {
        int j = wg;
        float s = 0.f, q = 0.f;
#pragma unroll
        for (int w2 = 0; w2 < 4; ++w2) {
            s += w_s[w2 * 16 + j * 2];
            q += w_s[w2 * 16 + j * 2 + 1];
        }
        int oc = ocg * 8 + j;
        int idx = (((head << 6) + oc) * 38 + r) * 2;
        g_part[idx]     = s;
        g_part[idx + 1] = q;
    }
}

// ---------------------------------------------------------------------------
template <bool RAW>
__global__ void __launch_bounds__(256, 2) conv_k8(
    const float* __restrict__ r0, const float* __restrict__ r1,
    const float* __restrict__ r2, const float* __restrict__ r3,
    const float* __restrict__ in0, const float* __restrict__ in1,
    const float* __restrict__ w0, const float* __restrict__ w1,
    const float* __restrict__ b0, const float* __restrict__ b1,
    float* __restrict__ out0, float* __restrict__ out1,
    int CIN, int g0) {

    __shared__ __align__(16) float in_s[2 * 2160];
    __shared__ __align__(16) float w_s[2 * 2 * 216];

    int gidx = blockIdx.x / 38;
    int r    = blockIdx.x - gidx * 38;
    int half = threadIdx.x >> 7;
    int head = (gidx >= g0);
    int lg   = head ? gidx - g0 : gidx;
    int ocg  = lg * 2 + half;

    const float* in   = head ? in1 : in0;
    const float* wgt  = head ? w1  : w0;
    const float* bias = head ? b1  : b0;
    float*       out  = head ? out1 : out0;
    float* wsl = w_s + half * (2 * 216);

    if (r < 32)
        conv_body8<0, RAW>(r, ocg, head, r, RAW ? r0 : in, wgt, bias, out, CIN, in_s, wsl);
    else if (r < 36)
        conv_body8<1, RAW>(r - 32, ocg, head, r, RAW ? r1 : in, wgt, bias, out, CIN, in_s, wsl);
    else if (r == 36)
        conv_body8<2, RAW>(0, ocg, head, r, RAW ? r2 : in, wgt, bias, out, CIN, in_s, wsl);
    else
        conv_body8<3, RAW>(0, ocg, head, r, RAW ? r3 : in, wgt, bias, out, CIN, in_s, wsl);
}

// ---------------------------------------------------------------------------
// VW=4 final conv body (channels-last output to d_out). 128 threads. (R10)
// ---------------------------------------------------------------------------
template <int LEV, int OCW>
__device__ __forceinline__ void conv_body4(
    int sp, int ocg,
    const float* __restrict__ in, const float* __restrict__ wgt,
    const float* __restrict__ bias, float* __restrict__ out,
    int CIN, int COUT, int head_base,
    float* __restrict__ in_s, float* __restrict__ w_s) {

    typedef Geo4<LEV> G;
    constexpr int S = G::S, PS = G::PS, OFF = G::OFF, VOX = G::VOX;
    constexpr int ZT = G::ZT, YT = G::YT, XT = G::XT, XP = G::XP;
    constexpr int TILE = ZT * YT * XP;
    constexpr int TOTE = ZT * YT * XT;
    constexpr int NL   = (TOTE + 127) / 128;

    const int t = threadIdx.x;
    int tz, ty, tx, d0 = 0, h0 = 0;
    bool active = true;
    if (LEV == 0) { tx = t & 7; ty = (t >> 3) & 7; tz = t >> 6;
                    d0 = (sp >> 2) * 2; h0 = (sp & 3) * 8; }
    else if (LEV == 1) { tx = t & 3; ty = (t >> 2) & 7; tz = t >> 5;
                    d0 = (sp >> 1) * 4; h0 = (sp & 1) * 8; }
    else if (LEV == 2) { tx = t & 1; ty = (t >> 1) & 7; tz = t >> 4; }
    else { tx = 0; ty = t & 3; tz = (t >> 2) & 3; active = (t < 16); }

    int goff[NL], sbyte[NL];
#pragma unroll
    for (int i = 0; i < NL; ++i) {
        int idx = i * 128 + t;
        sbyte[i] = -1;
        if (idx < TOTE) {
            int z = idx / (YT * XT), rem = idx - z * (YT * XT);
            int y = rem / XT, x = rem - y * XT;
            goff[i]  = ((d0 + z) * PS + (h0 + y)) * PS + x;
            sbyte[i] = ((z * YT + y) * XP + x) * 4;
        }
    }
    int wgoff[2];
    bool wok[2];
#pragma unroll
    for (int p = 0; p < 2; ++p) {
        int i = p * 128 + t;
        wgoff[p] = 0; wok[p] = false;
        if (i < 216) {
            int k = i >> 3, j = i & 7;
            int oc = ocg * OCW + j;
            if (j < OCW && oc < COUT) {
                wgoff[p] = (oc * CIN) * 27 + k;
                wok[p] = true;
            }
        }
    }

    const uint32_t in_sa = (uint32_t)__cvta_generic_to_shared(in_s);
    const uint32_t w_sa  = (uint32_t)__cvta_generic_to_shared(w_s);

    float acc[OCW][4];
#pragma unroll
    for (int j = 0; j < OCW; ++j) {
        acc[j][0] = 0.f; acc[j][1] = 0.f; acc[j][2] = 0.f; acc[j][3] = 0.f;
    }

    const float* inb = in + OFF;

    for (int i = t; i < 2 * 216; i += 128) w_s[i] = 0.f;
    __syncthreads();

    auto issue = [&](int b, int ic) {
        const float* src = inb + ic * CST;
#pragma unroll
        for (int i = 0; i < NL; ++i)
            if (sbyte[i] >= 0) cp4(in_sa + b * (TILE * 4) + sbyte[i], src + goff[i]);
#pragma unroll
        for (int p = 0; p < 2; ++p)
            if (wok[p]) cp4(w_sa + b * (216 * 4) + (p * 128 + t) * 4,
                            wgt + ic * 27 + wgoff[p]);
    };

    issue(0, 0);
    CP_COMMIT();
    CP_WAIT0();
    __syncthreads();

    for (int ic = 0; ic < CIN; ++ic) {
        int cur = ic & 1, nb = cur ^ 1;
        if (ic + 1 < CIN) { issue(nb, ic + 1); CP_COMMIT(); }

        if (active) {
            const float* buf = in_s + cur * TILE;
            const float* wb  = w_s + cur * 216;
#pragma unroll
            for (int kz = 0; kz < 3; ++kz) {
#pragma unroll
                for (int ky = 0; ky < 3; ++ky) {
                    const float* ip = &buf[((tz + kz) * YT + (ty + ky)) * XP + (tx << 2)];
                    float4 xa = *(const float4*)ip;
                    float2 xb = *(const float2*)(ip + 4);
                    float x0 = xa.x, x1 = xa.y, x2 = xa.z;
                    float x3 = xa.w, x4 = xb.x, x5 = xb.y;

                    const float* wt = wb + (kz * 3 + ky) * 24;
                    float w0a[8], w1a[8], w2a[8];
                    *(float4*)&w0a[0] = *(const float4*)(wt);
                    *(float4*)&w0a[4] = *(const float4*)(wt + 4);
                    *(float4*)&w1a[0] = *(const float4*)(wt + 8);
                    *(float4*)&w1a[4] = *(const float4*)(wt + 12);
                    *(float4*)&w2a[0] = *(const float4*)(wt + 16);
                    *(float4*)&w2a[4] = *(const float4*)(wt + 20);
#pragma unroll
                    for (int j = 0; j < OCW; ++j) {
                        float w0 = w0a[j], w1 = w1a[j], w2 = w2a[j];
                        acc[j][0] = fmaf(x0, w0, acc[j][0]);
                        acc[j][1] = fmaf(x1, w0, acc[j][1]);
                        acc[j][2] = fmaf(x2, w0, acc[j][2]);
                        acc[j][3] = fmaf(x3, w0, acc[j][3]);
                        acc[j][0] = fmaf(x1, w1, acc[j][0]);
                        acc[j][1] = fmaf(x2, w1, acc[j][1]);
                        acc[j][2] = fmaf(x3, w1, acc[j][2]);
                        acc[j][3] = fmaf(x4, w1, acc[j][3]);
                        acc[j][0] = fmaf(x2, w2, acc[j][0]);
                        acc[j][1] = fmaf(x3, w2, acc[j][1]);
                        acc[j][2] = fmaf(x4, w2, acc[j][2]);
                        acc[j][3] = fmaf(x5, w2, acc[j][3]);
                    }
                }
            }
        }

        if (ic + 1 < CIN) CP_WAIT0();
        __syncthreads();
    }

    if (!active) return;
    int d = d0 + tz, h = h0 + ty, w0i = tx << 2;
    int vidx = (d * S + h) * S + w0i;
#pragma unroll
    for (int j = 0; j < OCW; ++j) {
        int oc = ocg * OCW + j;
        if (oc >= COUT) break;
        float b = bias[oc];
        int base = head_base + (VOX + vidx) * COUT + oc;
        out[base + 0 * COUT] = acc[j][0] + b;
        out[base + 1 * COUT] = acc[j][1] + b;
        out[base + 2 * COUT] = acc[j][2] + b;
        out[base + 3 * COUT] = acc[j][3] + b;
    }
}

// ---------------------------------------------------------------------------
template <int OCW>
__global__ void __launch_bounds__(128) conv_kf(
    const float* __restrict__ in0, const float* __restrict__ in1,
    const float* __restrict__ w0, const float* __restrict__ w1,
    const float* __restrict__ b0, const float* __restrict__ b1,
    float* __restrict__ out,
    int CIN, int COUT0, int COUT1, int g0, int base1) {

    __shared__ __align__(16) float in_s[2 * 1440];
    __shared__ __align__(16) float w_s[2 * 216];

    int gidx = blockIdx.x / 74;
    int r    = blockIdx.x - gidx * 74;
    int head = (gidx >= g0);
    int ocg  = head ? gidx - g0 : gidx;

    const float* in   = head ? in1 : in0;
    const float* wgt  = head ? w1  : w0;
    const float* bias = head ? b1  : b0;
    int COUT  = head ? COUT1 : COUT0;
    int hbase = head ? base1 : 0;

    if (r < 64)
        conv_body4<0, OCW>(r, ocg, in, wgt, bias, out, CIN, COUT, hbase, in_s, w_s);
    else if (r < 72)
        conv_body4<1, OCW>(r - 64, ocg, in, wgt, bias, out, CIN, COUT, hbase, in_s, w_s);
    else if (r == 72)
        conv_body4<2, OCW>(0, ocg, in, wgt, bias, out, CIN, COUT, hbase, in_s, w_s);
    else
        conv_body4<3, OCW>(0, ocg, in, wgt, bias, out, CIN, COUT, hbase, in_s, w_s);
}

// ---------------------------------------------------------------------------
extern "C" void kernel_launch(void* const* d_in, const int* in_sizes, int n_in,
                              void* d_out, int out_size) {
    (void)in_sizes; (void)n_in; (void)out_size;

    const float* p0 = (const float*)d_in[0];
    const float* p1 = (const float*)d_in[1];
    const float* p2 = (const float*)d_in[2];
    const float* p3 = (const float*)d_in[3];

    const float* cw1   = (const float*)d_in[4];
    const float* cb1   = (const float*)d_in[5];
    const float* cw234 = (const float*)d_in[6];
    const float* cb234 = (const float*)d_in[7];
    const float* ca    = (const float*)d_in[8];
    const float* cwf   = (const float*)d_in[9];
    const float* cbf   = (const float*)d_in[10];
    const float* rw1   = (const float*)d_in[11];
    const float* rb1   = (const float*)d_in[12];
    const float* rw234 = (const float*)d_in[13];
    const float* rb234 = (const float*)d_in[14];
    const float* ra    = (const float*)d_in[15];
    const float* rwf   = (const float*)d_in[16];
    const float* rbf   = (const float*)d_in[17];

    float *buf, *mean, *rstd;
    cudaGetSymbolAddress((void**)&buf,  g_buf);
    cudaGetSymbolAddress((void**)&mean, g_mean);
    cudaGetSymbolAddress((void**)&rstd, g_rstd);

    float* A0 = buf;
    float* B0 = buf + (size_t)64 * CST;
    float* A1 = buf + (size_t)2 * 64 * CST;
    float* B1 = buf + (size_t)3 * 64 * CST;
    float* out = (float*)d_out;
    const int CLS_TOTAL = 37440 * 18;

    // conv1 (36->64) reading RAW inputs directly; epilogue writes partials
    conv_k8<true><<<8 * 38, 256>>>(p0, p1, p2, p3, A0, A1,
                                   cw1, rw1, cb1, rb1, A0, A1, 36, 4);
    reduce_kernel<<<512, 32>>>(mean, rstd);
    np_kernel<<<dim3(147, 64, 2), 256>>>(A0, A1, mean, rstd, ca, ra, 0);

    float* s0 = A0; float* d0p = B0;
    float* s1 = A1; float* d1p = B1;
    for (int i = 0; i < 3; ++i) {
        conv_k8<false><<<8 * 38, 256>>>(
            p0, p1, p2, p3, s0, s1,
            cw234 + (size_t)i * 64 * 64 * 27, rw234 + (size_t)i * 64 * 64 * 27,
            cb234 + i * 64, rb234 + i * 64, d0p, d1p, 64, 4);
        reduce_kernel<<<512, 32>>>(mean, rstd);
        np_kernel<<<dim3(147, 64, 2), 256>>>(d0p, d1p, mean, rstd, ca, ra, i + 1);
        float* t0 = s0; s0 = d0p; d0p = t0;
        float* t1 = s1; s1 = d1p; d1p = t1;
    }

    // final conv (R10 VW4/OCW6): cls 3 groups, reg 9 groups
    conv_kf<6><<<12 * 74, 128>>>(
        s0, s1, cwf, rwf, cbf, rbf, out, 64, 18, 54, 3, CLS_TOTAL);
}